// round 11
// baseline (speedup 1.0000x reference)
#include <cuda_runtime.h>
#include <math.h>

// ---------------------------------------------------------------------------
// SuperPointMatching_OT — 3 launches:
//   k_stream  (8194 blks): pure stream -> hit bitmap; blk0: reset + log tables
//   k_process (2048 blks): bitmap hits -> log-prefilter -> hist + candidates;
//                          last finished block computes the threshold
//   k_finish  (296 blks, persistent): gated fallbacks, compact, rank, output
// inner[i,j] = exp(ms[i,j]) * ref[i] * src[j]; stride 8193
// thres = first t in {0.5, 0.5-0.01f, ...} with count(inner > t) >= 2048
// out (24576 f32): ref_idx[8192] | src_idx[8192] | scores[8192]
// ---------------------------------------------------------------------------

#define STRIDE   8193u
#define NELEM    (8193u * 8193u)     // 67,125,249; last elem = dustbin corner
#define NVEC     (NELEM / 4u)        // 16,781,312 = 8194*2048 exactly
#define NWORDS   (NVEC / 32u)        // 524,416 bitmap words
#define TOTAL    (8192u * 8192u)
#define KCORR    2048u
#define MAXCORR  8192
#define NTHRES   64
#define K_SPEC   45                  // speculative cutoff bucket (T[45]~0.05)
#define LOGCUT   (-3.0f)             // exp(-3)<T[45], ref*src<1 => safe reject
#define LMARGIN  0.01f               // log-prefilter safety margin
#define CAP      (1024u * 1024u)
#define FCAP     65536u
#define SCAND    2048u
#define SHALF    4096u               // staging halves inside 32KB sBuf
#define NB_A     8194u
#define NB_P     2048u
#define NB_F     296u                // 2/SM x 148 SMs co-resident
#define NTH      256u

__device__ unsigned dBitmap[NWORDS];
__device__ float    dLref[8192], dLsrc[8192];
__device__ unsigned dHist[NTHRES];
__device__ float    dThres;
__device__ unsigned dDeep, dRecollect;
__device__ unsigned dCollected, dNF;
__device__ unsigned dDone;                 // monotonic (k_process completion)
__device__ unsigned gC, gR;                // monotonic grid barrier (k_finish)
__device__ unsigned dCandIdx[CAP];
__device__ float    dCandVal[CAP];
__device__ unsigned dFIdx[FCAP];
__device__ float    dFVal[FCAP];

__device__ __forceinline__ void build_table(float* T) {
    float t = 0.5f;
#pragma unroll
    for (int k = 0; k < NTHRES; k++) { T[k] = t; t = t - 0.01f; }
}

// Smallest k in [0, kmax] with v > T[k].
__device__ __forceinline__ int find_bucket(float v, const float* T, int kmax) {
    int k = (int)((0.5f - v) * 100.0f) - 2;
    k = k < 0 ? 0 : (k > kmax ? kmax : k);
    while (k > 0 && v > T[k - 1]) k--;
    while (k < kmax && !(v > T[k])) k++;
    return k;
}

__device__ __forceinline__ void grid_bar() {
    __syncthreads();
    if (threadIdx.x == 0) {
        __threadfence();
        unsigned arrival = atomicAdd(&gC, 1u) + 1u;
        unsigned target = ((arrival + NB_F - 1u) / NB_F) * NB_F;
        if (arrival == target) atomicMax(&gR, target);
        else while (atomicAdd(&gR, 0u) < target) __nanosleep(64);
        __threadfence();
    }
    __syncthreads();
}

// ---------------------------------------------------------------------------
// K1: pure stream. 1 bit per float4 (max component > LOGCUT). Fills output,
// resets per-replay state, builds log tables (block 0).
__global__ void __launch_bounds__(NTH) k_stream(const float4* __restrict__ ms4,
                                                const float* __restrict__ refw,
                                                const float* __restrict__ srcw,
                                                float* __restrict__ out,
                                                int out_size) {
    const unsigned tid = threadIdx.x;
    const unsigned w = tid >> 5, l = tid & 31u;
    const unsigned base = blockIdx.x * 2048u;

    unsigned gid = blockIdx.x * NTH + tid;
    if (gid < (unsigned)out_size)
        out[gid] = (gid < 2u * MAXCORR) ? -1.0f : 0.0f;

    if (blockIdx.x == 0) {                       // housekeeping, in parallel
        if (tid < NTHRES) dHist[tid] = 0u;
        if (tid == 64u) { dCollected = 0u; dNF = 0u; }
        if (tid == 65u) { dDeep = 0u; dRecollect = 0u; dThres = 0.0f; }
        for (unsigned p = tid; p < 8192u; p += NTH) {
            dLref[p] = __logf(refw[p]);
            dLsrc[p] = __logf(srcw[p]);
        }
    }

    float4 a[8];
#pragma unroll
    for (int k = 0; k < 8; k++)
        a[k] = __ldcs(ms4 + base + (unsigned)k * 256u + w * 32u + l);

    unsigned word = 0u;
#pragma unroll
    for (int k = 0; k < 8; k++) {
        float mx = fmaxf(fmaxf(a[k].x, a[k].y), fmaxf(a[k].z, a[k].w));
        unsigned msk = __ballot_sync(0xFFFFFFFFu, mx > LOGCUT);
        if (l == (unsigned)k) word = msk;
    }
    if (l < 8u) dBitmap[blockIdx.x * 64u + l * 8u + w] = word;
}

// ---------------------------------------------------------------------------
// K2: bitmap hits -> log prefilter -> expf only for near/above-tspec elems.
// Shared candidate staging; last finished block computes the threshold.
__global__ void __launch_bounds__(NTH) k_process(const float4* __restrict__ ms4,
                                                 const float* __restrict__ refw,
                                                 const float* __restrict__ srcw) {
    __shared__ float    T[NTHRES];
    __shared__ unsigned sHist[NTHRES];
    __shared__ unsigned sN, sBase, sLast;
    __shared__ unsigned sIdx[SCAND];
    __shared__ float    sVal[SCAND];

    const unsigned tid = threadIdx.x;
    if (tid == 0) { build_table(T); sN = 0u; }
    if (tid < NTHRES) sHist[tid] = 0u;
    __syncthreads();
    const float tspec = T[K_SPEC];
    const float logcut2 = __logf(tspec) - LMARGIN;   // conservative log bound

    const unsigned step = NB_P * NTH;
    for (unsigned wi = blockIdx.x * NTH + tid; wi < NWORDS; wi += step) {
        unsigned word = dBitmap[wi];
        while (word) {
            int b = __ffs(word) - 1; word &= word - 1u;
            unsigned vp = wi * 32u + (unsigned)b;
            float4 a = __ldg(ms4 + vp);
            float mv[4] = {a.x, a.y, a.z, a.w};
#pragma unroll
            for (int c = 0; c < 4; c++) {
                float m = mv[c];
                if (m > LOGCUT) {
                    unsigned pe = vp * 4u + (unsigned)c;
                    unsigned i = pe / STRIDE;
                    unsigned j = pe - i * STRIDE;
                    if (i < 8192u && j < 8192u &&
                        m + dLref[i] + dLsrc[j] > logcut2) {   // cheap reject
                        float v = __fmul_rn(expf(m),
                                            __fmul_rn(refw[i], srcw[j]));
                        if (v > tspec) {
                            atomicAdd(&sHist[find_bucket(v, T, K_SPEC)], 1u);
                            unsigned p = atomicAdd(&sN, 1u);
                            if (p < SCAND) { sIdx[p] = (i << 13) | j; sVal[p] = v; }
                            else {
                                unsigned g = atomicAdd(&dCollected, 1u);
                                if (g < CAP) { dCandIdx[g] = (i << 13) | j;
                                               dCandVal[g] = v; }
                            }
                        }
                    }
                }
            }
        }
    }
    __syncthreads();
    if (tid < NTHRES && sHist[tid]) atomicAdd(&dHist[tid], sHist[tid]);
    if (tid == 0) {
        unsigned n = sN < SCAND ? sN : SCAND;
        sBase = atomicAdd(&dCollected, n);
    }
    __syncthreads();
    unsigned n = sN < SCAND ? sN : SCAND;
    for (unsigned p = tid; p < n; p += NTH) {
        unsigned g = sBase + p;
        if (g < CAP) { dCandIdx[g] = sIdx[p]; dCandVal[g] = sVal[p]; }
    }

    // --- last-block threshold selection ---
    __threadfence();
    __syncthreads();
    if (tid == 0) {
        unsigned a = atomicAdd(&dDone, 1u) + 1u;   // monotonic across replays
        sLast = (a % NB_P == 0u) ? 1u : 0u;
    }
    __syncthreads();
    if (sLast) {
        __threadfence();
        if (tid < NTHRES) sHist[tid] = atomicAdd(&dHist[tid], 0u);
        __syncthreads();
        if (tid == 0) {
            unsigned cum = 0; int ks = -1;
            for (int k = 0; k <= K_SPEC; k++) {
                cum += sHist[k];
                if (cum >= KCORR) { ks = k; break; }
            }
            if (ks < 0) { dDeep = 1u; dRecollect = 1u; dCollected = 0u; }
            else {
                dThres = T[ks];
                if (atomicAdd(&dCollected, 0u) > CAP) {
                    dRecollect = 1u; dCollected = 0u;
                }
            }
            __threadfence();
        }
    }
}

// ---------------------------------------------------------------------------
// K3: persistent. Gated fallbacks (deep hist / recollect), compact, rank.
__global__ void __launch_bounds__(NTH, 2)
k_finish(const float* __restrict__ ms, const float* __restrict__ refw,
         const float* __restrict__ srcw, float* __restrict__ out)
{
    __shared__ float    T[NTHRES];
    __shared__ unsigned sHist[NTHRES];
    __shared__ unsigned sN, sBase;
    __shared__ unsigned sBuf[8192];              // 32KB multi-purpose

    const unsigned tid = threadIdx.x;
    const unsigned gid = blockIdx.x * NTH + tid;
    const unsigned step = NB_F * NTH;

    if (tid == 0) { build_table(T); sN = 0u; }
    if (tid < NTHRES) sHist[tid] = 0u;
    __syncthreads();
    const float tspec = T[K_SPEC];

    const unsigned deep = dDeep;                 // grid-uniform (set pre-launch)
    const unsigned rec  = dRecollect;

    // ---- fallback 1: full-depth histogram ----------------------------------
    if (deep) {
        unsigned short (*h)[32] = (unsigned short (*)[32])sBuf;  // [8*64][32]
        for (unsigned p = tid; p < 8192u; p += NTH) sBuf[p] = 0u;
        __syncthreads();
        unsigned wrp = tid >> 5, lane = tid & 31u;
        for (unsigned idx = gid; idx < TOTAL; idx += step) {
            unsigned i = idx >> 13, j = idx & 8191u;
            float m = __ldg(ms + i * STRIDE + j);
            float v = __fmul_rn(expf(m), __fmul_rn(refw[i], srcw[j]));
            if (!(v > tspec)) {                  // buckets <=K_SPEC already done
                int k = find_bucket(v, T, NTHRES - 1);
                h[wrp * NTHRES + k][lane]++;
            }
        }
        __syncthreads();
        if (tid < NTHRES) {
            unsigned s = 0;
            for (int wq = 0; wq < 8; wq++)
                for (int lq = 0; lq < 32; lq++) s += h[wq * NTHRES + tid][lq];
            if (s) atomicAdd(&dHist[tid], s);
        }
        grid_bar();
        if (blockIdx.x == 0 && tid == 0) {
            unsigned cum = 0; int ks = NTHRES - 1;
            for (int k = 0; k < NTHRES; k++) {
                cum += dHist[k];
                if (cum >= KCORR) { ks = k; break; }
            }
            dThres = T[ks];
            __threadfence();
        }
        grid_bar();
    }

    // ---- fallback 2: re-collect with final threshold ------------------------
    if (rec) {
        unsigned* sIdx = sBuf;
        float*    sVal = (float*)(sBuf + SHALF);
        const float th = dThres;
        float lcut = (th > 1e-30f) ? (logf(th) - 0.02f) : -1e30f;
        for (unsigned idx = gid; idx < TOTAL; idx += step) {
            unsigned i = idx >> 13, j = idx & 8191u;
            float m = __ldg(ms + i * STRIDE + j);
            if (m > lcut) {
                float v = __fmul_rn(expf(m), __fmul_rn(refw[i], srcw[j]));
                if (v > th) {
                    unsigned p = atomicAdd(&sN, 1u);
                    if (p < SHALF) { sIdx[p] = (i << 13) | j; sVal[p] = v; }
                    else {
                        unsigned g = atomicAdd(&dCollected, 1u);
                        if (g < CAP) { dCandIdx[g] = (i << 13) | j; dCandVal[g] = v; }
                    }
                }
            }
        }
        __syncthreads();
        if (tid == 0) {
            unsigned n = sN < SHALF ? sN : SHALF;
            sBase = atomicAdd(&dCollected, n);
        }
        __syncthreads();
        unsigned n = sN < SHALF ? sN : SHALF;
        for (unsigned p = tid; p < n; p += NTH) {
            unsigned g = sBase + p;
            if (g < CAP) { dCandIdx[g] = sIdx[p]; dCandVal[g] = sVal[p]; }
        }
        __syncthreads();
        if (tid == 0) sN = 0u;
        grid_bar();
    }

    // ---- compact: candidates above final threshold (shared staging) --------
    {
        unsigned* sIdx = sBuf;
        float*    sVal = (float*)(sBuf + SHALF);
        unsigned n = atomicAdd(&dCollected, 0u); if (n > CAP) n = CAP;
        float th = dThres;
        for (unsigned q = gid; q < n; q += step) {
            float v = dCandVal[q];
            if (v > th) {
                unsigned p = atomicAdd(&sN, 1u);
                if (p < SHALF) { sIdx[p] = dCandIdx[q]; sVal[p] = v; }
                else {
                    unsigned g = atomicAdd(&dNF, 1u);
                    if (g < FCAP) { dFIdx[g] = dCandIdx[q]; dFVal[g] = v; }
                }
            }
        }
        __syncthreads();
        if (tid == 0) {
            unsigned m = sN < SHALF ? sN : SHALF;
            sBase = atomicAdd(&dNF, m);
        }
        __syncthreads();
        unsigned m = sN < SHALF ? sN : SHALF;
        for (unsigned p = tid; p < m; p += NTH) {
            unsigned g = sBase + p;
            if (g < FCAP) { dFIdx[g] = sIdx[p]; dFVal[g] = sVal[p]; }
        }
    }
    grid_bar();

    // ---- rank (row-major position) + ordered write --------------------------
    {
        unsigned nF = atomicAdd(&dNF, 0u); if (nF > FCAP) nF = FCAP;
        if (blockIdx.x * NTH < nF) {                 // block-uniform skip
            unsigned Li = (gid < nF) ? dFIdx[gid] : 0xFFFFFFFFu;
            float    Vi = (gid < nF) ? dFVal[gid] : 0.0f;
            unsigned rank = 0;
            for (unsigned base = 0; base < nF; base += 8192u) {
                unsigned m = nF - base; if (m > 8192u) m = 8192u;
                __syncthreads();
                for (unsigned p = tid; p < m; p += NTH) sBuf[p] = dFIdx[base + p];
                __syncthreads();
                if (gid < nF)
                    for (unsigned p = 0; p < m; p++) rank += (sBuf[p] < Li) ? 1u : 0u;
            }
            if (gid < nF && rank < (unsigned)MAXCORR) {
                unsigned r = Li >> 13, c = Li & 8191u;
                out[rank]               = (float)r;
                out[MAXCORR + rank]     = (float)c;
                out[2 * MAXCORR + rank] = Vi;
            }
        }
    }
}

// ---------------------------------------------------------------------------
extern "C" void kernel_launch(void* const* d_in, const int* in_sizes, int n_in,
                              void* d_out, int out_size) {
    const float* ms   = (const float*)d_in[0];   // (8193, 8193) f32
    const float* refw = (const float*)d_in[1];   // (8192,) f32
    const float* srcw = (const float*)d_in[2];   // (8192,) f32
    float* out = (float*)d_out;                  // 24576 f32

    k_stream<<<NB_A, NTH>>>((const float4*)ms, refw, srcw, out, out_size);
    k_process<<<NB_P, NTH>>>((const float4*)ms, refw, srcw);
    k_finish<<<NB_F, NTH>>>(ms, refw, srcw, out);
}

// round 15
// speedup vs baseline: 1.8562x; 1.8562x over previous
#include <cuda_runtime.h>
#include <math.h>

// ---------------------------------------------------------------------------
// SuperPointMatching_OT — 3 launches:
//   k_stream  (8194 blks): pure stream -> hit bitmap; blk0: reset + log tables
//   k_process (2048 blks): bitmap hits -> log-prefilter -> hist + candidates;
//                          last finished block computes the threshold
//   k_finish  (296 blks, persistent): gated fallbacks, compact, rank, output
// inner[i,j] = exp(ms[i,j]) * ref[i] * src[j]; stride 8193
// thres = first t in {0.5, 0.5-0.01f, ...} with count(inner > t) >= 2048
// out (24576 f32): ref_idx[8192] | src_idx[8192] | scores[8192]
// ---------------------------------------------------------------------------

#define STRIDE   8193u
#define NELEM    (8193u * 8193u)     // 67,125,249; last elem = dustbin corner
#define NVEC     (NELEM / 4u)        // 16,781,312 = 8194*2048 exactly
#define NWORDS   (NVEC / 32u)        // 524,416 bitmap words
#define TOTAL    (8192u * 8192u)
#define KCORR    2048u
#define MAXCORR  8192
#define NTHRES   64
#define K_SPEC   45                  // speculative cutoff bucket (T[45]~0.05)
#define LOGCUT   (-3.0f)             // exp(-3)<T[45], ref*src<1 => safe reject
#define LMARGIN  0.01f               // log-prefilter safety margin
#define CAP      (1024u * 1024u)
#define FCAP     65536u
#define SCAND    2048u
#define SHALF    4096u               // staging halves inside 32KB sBuf
#define NB_A     8194u
#define NB_P     2048u
#define NB_F     296u                // 2/SM x 148 SMs co-resident
#define NTH      256u

__device__ unsigned dBitmap[NWORDS];
__device__ float    dLref[8192], dLsrc[8192];
__device__ unsigned dHist[NTHRES];
__device__ float    dThres;
__device__ unsigned dDeep, dRecollect;
__device__ unsigned dCollected, dNF;
__device__ unsigned dDone;                 // monotonic (k_process completion)
__device__ unsigned gC, gR;                // monotonic grid barrier (k_finish)
__device__ unsigned dCandIdx[CAP];
__device__ float    dCandVal[CAP];
__device__ unsigned dFIdx[FCAP];
__device__ float    dFVal[FCAP];

__device__ __forceinline__ void build_table(float* T) {
    float t = 0.5f;
#pragma unroll
    for (int k = 0; k < NTHRES; k++) { T[k] = t; t = t - 0.01f; }
}

// Smallest k in [0, kmax] with v > T[k].
__device__ __forceinline__ int find_bucket(float v, const float* T, int kmax) {
    int k = (int)((0.5f - v) * 100.0f) - 2;
    k = k < 0 ? 0 : (k > kmax ? kmax : k);
    while (k > 0 && v > T[k - 1]) k--;
    while (k < kmax && !(v > T[k])) k++;
    return k;
}

// L2 (cg) scalar loads — bypass possibly-stale L1, no atomic serialization.
__device__ __forceinline__ unsigned ldcg_u(const unsigned* p) {
    unsigned v;
    asm volatile("ld.global.cg.u32 %0, [%1];" : "=r"(v) : "l"(p));
    return v;
}
__device__ __forceinline__ float ldcg_f(const float* p) {
    float v;
    asm volatile("ld.global.cg.f32 %0, [%1];" : "=f"(v) : "l"(p));
    return v;
}

__device__ __forceinline__ void grid_bar() {
    __syncthreads();
    if (threadIdx.x == 0) {
        __threadfence();
        unsigned arrival = atomicAdd(&gC, 1u) + 1u;
        unsigned target = ((arrival + NB_F - 1u) / NB_F) * NB_F;
        if (arrival == target) atomicMax(&gR, target);
        else while (atomicAdd(&gR, 0u) < target) __nanosleep(64);
        __threadfence();
    }
    __syncthreads();
}

// ---------------------------------------------------------------------------
// K1: pure stream. 1 bit per float4 (max component > LOGCUT). Fills output,
// resets per-replay state, builds log tables (block 0).
__global__ void __launch_bounds__(NTH) k_stream(const float4* __restrict__ ms4,
                                                const float* __restrict__ refw,
                                                const float* __restrict__ srcw,
                                                float* __restrict__ out,
                                                int out_size) {
    const unsigned tid = threadIdx.x;
    const unsigned w = tid >> 5, l = tid & 31u;
    const unsigned base = blockIdx.x * 2048u;

    unsigned gid = blockIdx.x * NTH + tid;
    if (gid < (unsigned)out_size)
        out[gid] = (gid < 2u * MAXCORR) ? -1.0f : 0.0f;

    if (blockIdx.x == 0) {                       // housekeeping, in parallel
        if (tid < NTHRES) dHist[tid] = 0u;
        if (tid == 64u) { dCollected = 0u; dNF = 0u; }
        if (tid == 65u) { dDeep = 0u; dRecollect = 0u; dThres = 0.0f; }
        for (unsigned p = tid; p < 8192u; p += NTH) {
            dLref[p] = __logf(refw[p]);
            dLsrc[p] = __logf(srcw[p]);
        }
    }

    float4 a[8];
#pragma unroll
    for (int k = 0; k < 8; k++)
        a[k] = __ldcs(ms4 + base + (unsigned)k * 256u + w * 32u + l);

    unsigned word = 0u;
#pragma unroll
    for (int k = 0; k < 8; k++) {
        float mx = fmaxf(fmaxf(a[k].x, a[k].y), fmaxf(a[k].z, a[k].w));
        unsigned msk = __ballot_sync(0xFFFFFFFFu, mx > LOGCUT);
        if (l == (unsigned)k) word = msk;
    }
    if (l < 8u) dBitmap[blockIdx.x * 64u + l * 8u + w] = word;
}

// ---------------------------------------------------------------------------
// K2: bitmap hits -> log prefilter -> expf only for near/above-tspec elems.
// Shared candidate staging; last finished block computes the threshold.
__global__ void __launch_bounds__(NTH) k_process(const float4* __restrict__ ms4,
                                                 const float* __restrict__ refw,
                                                 const float* __restrict__ srcw) {
    __shared__ float    T[NTHRES];
    __shared__ unsigned sHist[NTHRES];
    __shared__ unsigned sN, sBase, sLast;
    __shared__ unsigned sIdx[SCAND];
    __shared__ float    sVal[SCAND];

    const unsigned tid = threadIdx.x;
    if (tid == 0) { build_table(T); sN = 0u; }
    if (tid < NTHRES) sHist[tid] = 0u;
    __syncthreads();
    const float tspec = T[K_SPEC];
    const float logcut2 = __logf(tspec) - LMARGIN;   // conservative log bound

    const unsigned step = NB_P * NTH;
    for (unsigned wi = blockIdx.x * NTH + tid; wi < NWORDS; wi += step) {
        unsigned word = dBitmap[wi];
        while (word) {
            int b = __ffs(word) - 1; word &= word - 1u;
            unsigned vp = wi * 32u + (unsigned)b;
            float4 a = __ldg(ms4 + vp);
            float mv[4] = {a.x, a.y, a.z, a.w};
#pragma unroll
            for (int c = 0; c < 4; c++) {
                float m = mv[c];
                if (m > LOGCUT) {
                    unsigned pe = vp * 4u + (unsigned)c;
                    unsigned i = pe / STRIDE;
                    unsigned j = pe - i * STRIDE;
                    if (i < 8192u && j < 8192u &&
                        m + dLref[i] + dLsrc[j] > logcut2) {   // cheap reject
                        float v = __fmul_rn(expf(m),
                                            __fmul_rn(refw[i], srcw[j]));
                        if (v > tspec) {
                            atomicAdd(&sHist[find_bucket(v, T, K_SPEC)], 1u);
                            unsigned p = atomicAdd(&sN, 1u);
                            if (p < SCAND) { sIdx[p] = (i << 13) | j; sVal[p] = v; }
                            else {
                                unsigned g = atomicAdd(&dCollected, 1u);
                                if (g < CAP) { dCandIdx[g] = (i << 13) | j;
                                               dCandVal[g] = v; }
                            }
                        }
                    }
                }
            }
        }
    }
    __syncthreads();
    if (tid < NTHRES && sHist[tid]) atomicAdd(&dHist[tid], sHist[tid]);
    if (tid == 0) {
        unsigned n = sN < SCAND ? sN : SCAND;
        sBase = atomicAdd(&dCollected, n);
    }
    __syncthreads();
    unsigned n = sN < SCAND ? sN : SCAND;
    for (unsigned p = tid; p < n; p += NTH) {
        unsigned g = sBase + p;
        if (g < CAP) { dCandIdx[g] = sIdx[p]; dCandVal[g] = sVal[p]; }
    }

    // --- last-block threshold selection (tiny; 64 atomic reads total) ---
    __threadfence();
    __syncthreads();
    if (tid == 0) {
        unsigned a = atomicAdd(&dDone, 1u) + 1u;   // monotonic across replays
        sLast = (a % NB_P == 0u) ? 1u : 0u;
    }
    __syncthreads();
    if (sLast) {
        __threadfence();
        if (tid < NTHRES) sHist[tid] = atomicAdd(&dHist[tid], 0u);
        __syncthreads();
        if (tid == 0) {
            unsigned cum = 0; int ks = -1;
            for (int k = 0; k <= K_SPEC; k++) {
                cum += sHist[k];
                if (cum >= KCORR) { ks = k; break; }
            }
            if (ks < 0) { dDeep = 1u; dRecollect = 1u; dCollected = 0u; }
            else {
                dThres = T[ks];
                if (atomicAdd(&dCollected, 0u) > CAP) {
                    dRecollect = 1u; dCollected = 0u;
                }
            }
            __threadfence();
        }
    }
}

// ---------------------------------------------------------------------------
// K3: persistent. Gated fallbacks (deep hist / recollect), compact, rank.
// ALL counter reads are plain ld.cg loads — never same-address atomics.
__global__ void __launch_bounds__(NTH, 2)
k_finish(const float* __restrict__ ms, const float* __restrict__ refw,
         const float* __restrict__ srcw, float* __restrict__ out)
{
    __shared__ float    T[NTHRES];
    __shared__ unsigned sN, sBase;
    __shared__ unsigned sBuf[8192];              // 32KB multi-purpose

    const unsigned tid = threadIdx.x;
    const unsigned gid = blockIdx.x * NTH + tid;
    const unsigned step = NB_F * NTH;

    if (tid == 0) { build_table(T); sN = 0u; }
    __syncthreads();
    const float tspec = T[K_SPEC];

    const unsigned deep = ldcg_u(&dDeep);        // grid-uniform (pre-launch)
    const unsigned rec  = ldcg_u(&dRecollect);

    // ---- fallback 1: full-depth histogram (normally skipped) ---------------
    if (deep) {
        unsigned short (*h)[32] = (unsigned short (*)[32])sBuf;  // [8*64][32]
        for (unsigned p = tid; p < 8192u; p += NTH) sBuf[p] = 0u;
        __syncthreads();
        unsigned wrp = tid >> 5, lane = tid & 31u;
        for (unsigned idx = gid; idx < TOTAL; idx += step) {
            unsigned i = idx >> 13, j = idx & 8191u;
            float m = __ldg(ms + i * STRIDE + j);
            float v = __fmul_rn(expf(m), __fmul_rn(refw[i], srcw[j]));
            if (!(v > tspec)) {                  // buckets <=K_SPEC already done
                int k = find_bucket(v, T, NTHRES - 1);
                h[wrp * NTHRES + k][lane]++;
            }
        }
        __syncthreads();
        if (tid < NTHRES) {
            unsigned s = 0;
            for (int wq = 0; wq < 8; wq++)
                for (int lq = 0; lq < 32; lq++) s += h[wq * NTHRES + tid][lq];
            if (s) atomicAdd(&dHist[tid], s);
        }
        grid_bar();
        if (blockIdx.x == 0 && tid == 0) {
            unsigned cum = 0; int ks = NTHRES - 1;
            for (int k = 0; k < NTHRES; k++) {
                cum += dHist[k];
                if (cum >= KCORR) { ks = k; break; }
            }
            dThres = T[ks];
            __threadfence();
        }
        grid_bar();
    }

    // ---- fallback 2: re-collect with final threshold (normally skipped) ----
    if (rec) {
        unsigned* sIdx = sBuf;
        float*    sVal = (float*)(sBuf + SHALF);
        const float th = ldcg_f(&dThres);
        float lcut = (th > 1e-30f) ? (logf(th) - 0.02f) : -1e30f;
        for (unsigned idx = gid; idx < TOTAL; idx += step) {
            unsigned i = idx >> 13, j = idx & 8191u;
            float m = __ldg(ms + i * STRIDE + j);
            if (m > lcut) {
                float v = __fmul_rn(expf(m), __fmul_rn(refw[i], srcw[j]));
                if (v > th) {
                    unsigned p = atomicAdd(&sN, 1u);
                    if (p < SHALF) { sIdx[p] = (i << 13) | j; sVal[p] = v; }
                    else {
                        unsigned g = atomicAdd(&dCollected, 1u);
                        if (g < CAP) { dCandIdx[g] = (i << 13) | j; dCandVal[g] = v; }
                    }
                }
            }
        }
        __syncthreads();
        if (tid == 0) {
            unsigned n = sN < SHALF ? sN : SHALF;
            sBase = atomicAdd(&dCollected, n);
        }
        __syncthreads();
        unsigned n = sN < SHALF ? sN : SHALF;
        for (unsigned p = tid; p < n; p += NTH) {
            unsigned g = sBase + p;
            if (g < CAP) { dCandIdx[g] = sIdx[p]; dCandVal[g] = sVal[p]; }
        }
        __syncthreads();
        if (tid == 0) sN = 0u;
        grid_bar();
    }

    // ---- compact: candidates above final threshold (shared staging) --------
    {
        unsigned* sIdx = sBuf;
        float*    sVal = (float*)(sBuf + SHALF);
        unsigned n = ldcg_u(&dCollected); if (n > CAP) n = CAP;   // plain ld.cg
        float th = ldcg_f(&dThres);
        for (unsigned q = gid; q < n; q += step) {
            float v = ldcg_f(&dCandVal[q]);
            if (v > th) {
                unsigned p = atomicAdd(&sN, 1u);
                unsigned id = ldcg_u(&dCandIdx[q]);
                if (p < SHALF) { sIdx[p] = id; sVal[p] = v; }
                else {
                    unsigned g = atomicAdd(&dNF, 1u);
                    if (g < FCAP) { dFIdx[g] = id; dFVal[g] = v; }
                }
            }
        }
        __syncthreads();
        if (tid == 0) {
            unsigned m = sN < SHALF ? sN : SHALF;
            sBase = atomicAdd(&dNF, m);
        }
        __syncthreads();
        unsigned m = sN < SHALF ? sN : SHALF;
        for (unsigned p = tid; p < m; p += NTH) {
            unsigned g = sBase + p;
            if (g < FCAP) { dFIdx[g] = sIdx[p]; dFVal[g] = sVal[p]; }
        }
    }
    grid_bar();

    // ---- rank (row-major position) + ordered write --------------------------
    {
        unsigned nF = ldcg_u(&dNF); if (nF > FCAP) nF = FCAP;     // plain ld.cg
        if (blockIdx.x * NTH < nF) {                 // block-uniform skip
            unsigned Li = (gid < nF) ? ldcg_u(&dFIdx[gid]) : 0xFFFFFFFFu;
            float    Vi = (gid < nF) ? ldcg_f(&dFVal[gid]) : 0.0f;
            unsigned rank = 0;
            for (unsigned base = 0; base < nF; base += 8192u) {
                unsigned m = nF - base; if (m > 8192u) m = 8192u;
                __syncthreads();
                for (unsigned p = tid; p < m; p += NTH)
                    sBuf[p] = ldcg_u(&dFIdx[base + p]);
                __syncthreads();
                if (gid < nF)
                    for (unsigned p = 0; p < m; p++) rank += (sBuf[p] < Li) ? 1u : 0u;
            }
            if (gid < nF && rank < (unsigned)MAXCORR) {
                unsigned r = Li >> 13, c = Li & 8191u;
                out[rank]               = (float)r;
                out[MAXCORR + rank]     = (float)c;
                out[2 * MAXCORR + rank] = Vi;
            }
        }
    }
}

// ---------------------------------------------------------------------------
extern "C" void kernel_launch(void* const* d_in, const int* in_sizes, int n_in,
                              void* d_out, int out_size) {
    const float* ms   = (const float*)d_in[0];   // (8193, 8193) f32
    const float* refw = (const float*)d_in[1];   // (8192,) f32
    const float* srcw = (const float*)d_in[2];   // (8192,) f32
    float* out = (float*)d_out;                  // 24576 f32

    k_stream<<<NB_A, NTH>>>((const float4*)ms, refw, srcw, out, out_size);
    k_process<<<NB_P, NTH>>>((const float4*)ms, refw, srcw);
    k_finish<<<NB_F, NTH>>>(ms, refw, srcw, out);
}